// round 1
// baseline (speedup 1.0000x reference)
#include <cuda_runtime.h>
#include <math.h>

// ---------------------------------------------------------------------------
// Problem constants
// ---------------------------------------------------------------------------
#define BATCH 2
#define VIEWS 6
#define CH    256
#define NQ    900
#define KKP   4
#define H0    64
#define W0    176
#define H1    32
#define W1    88
#define HEADS 8
#define HDIM  32

// ---------------------------------------------------------------------------
// Device scratch (static allocations only — no cudaMalloc allowed)
// ---------------------------------------------------------------------------
__device__ float g_feat0[(size_t)BATCH * VIEWS * H0 * W0 * CH]; // NHWC level 0
__device__ float g_feat1[(size_t)BATCH * VIEWS * H1 * W1 * CH]; // NHWC level 1
__device__ float g_ctx[BATCH * NQ * CH];
__device__ float g_qp [BATCH * NQ * CH];
__device__ float g_kp [BATCH * NQ * CH];
__device__ float g_vp [BATCH * NQ * CH];
__device__ float g_ao [BATCH * NQ * CH];

// ---------------------------------------------------------------------------
// Kernel 1: CHW -> HWC transpose (per (b,v) image), 32x32 smem tiles
// in : [BV, C, HW]   out : [BV, HW, C]
// ---------------------------------------------------------------------------
__global__ void transpose_nhwc_kernel(const float* __restrict__ in, int HW, int level) {
    __shared__ float tile[32][33];
    float* out = level ? g_feat1 : g_feat0;
    int bv = blockIdx.z;
    int c0 = blockIdx.y * 32;
    int p0 = blockIdx.x * 32;
    const float* inp = in  + (size_t)bv * CH * HW;
    float*      outp = out + (size_t)bv * HW * CH;

#pragma unroll
    for (int i = 0; i < 32; i += 8) {
        int c = c0 + threadIdx.y + i;
        int p = p0 + threadIdx.x;
        float v = (p < HW) ? inp[(size_t)c * HW + p] : 0.f;
        tile[threadIdx.y + i][threadIdx.x] = v;
    }
    __syncthreads();
#pragma unroll
    for (int i = 0; i < 32; i += 8) {
        int p = p0 + threadIdx.y + i;
        int c = c0 + threadIdx.x;
        if (p < HW) outp[(size_t)p * CH + c] = tile[threadIdx.x][threadIdx.y + i];
    }
}

// ---------------------------------------------------------------------------
// Kernel 2: multi-view multi-level sampler -> g_ctx[B,Q,C]
// One block per (b,q), 256 threads = channels.
// ---------------------------------------------------------------------------
__global__ __launch_bounds__(256) void sampler_kernel(
    const float* __restrict__ refs,   // [B,Q,3]
    const float* __restrict__ intr,   // [B,V,3,3]
    const float* __restrict__ extr)   // [B,V,4,4]
{
    int bq = blockIdx.x;
    int b  = bq / NQ;
    int c  = threadIdx.x;

    float rx = refs[bq * 3 + 0];
    float ry = refs[bq * 3 + 1];
    float rz = refs[bq * 3 + 2];

    const float kpx[KKP] = {0.f, 2.f, 0.f, -2.f};
    const float kpy[KKP] = {0.f, 0.f, 2.f, 0.f};

    float total = 0.f;

#pragma unroll
    for (int lev = 0; lev < 2; lev++) {
        const float* fm = lev ? g_feat1 : g_feat0;
        const int H = lev ? H1 : H0;
        const int W = lev ? W1 : W0;

        float acc = 0.f;
        float cnt = 0.f;

        for (int v = 0; v < VIEWS; v++) {
            const float* E  = extr + (size_t)(b * VIEWS + v) * 16;
            const float* Km = intr + (size_t)(b * VIEWS + v) * 9;
            const float* base = fm + (size_t)(b * VIEWS + v) * H * W * CH;

#pragma unroll
            for (int k = 0; k < KKP; k++) {
                float px = rx + kpx[k];
                float py = ry + kpy[k];
                float pz = rz;
                // camera coords = E(4x4) @ [p,1], rows 0..2
                float cxx = E[0]*px + E[1]*py + E[2]*pz  + E[3];
                float cyy = E[4]*px + E[5]*py + E[6]*pz  + E[7];
                float czz = E[8]*px + E[9]*py + E[10]*pz + E[11];
                // uvw = K(3x3) @ cam
                float u  = Km[0]*cxx + Km[1]*cyy + Km[2]*czz;
                float vv = Km[3]*cxx + Km[4]*cyy + Km[5]*czz;
                float w  = Km[6]*cxx + Km[7]*cyy + Km[8]*czz;

                bool valid = (w > 0.f);
                if (valid) cnt += 1.f;
                if (!valid) continue;   // contribution would be multiplied by 0

                float zs = (fabsf(w) > 1e-6f) ? w : 1e-6f;
                // gx = 2*(u/zs)/(W-1)-1 ; x = (gx+1)*0.5*(W-1) == u/zs
                float x = u / zs;
                float y = vv / zs;

                float x0 = floorf(x), y0 = floorf(y);
                float wx1 = x - x0, wx0 = 1.f - wx1;
                float wy1 = y - y0, wy0 = 1.f - wy1;

                bool xin0 = (x0       >= 0.f) && (x0       <= (float)(W - 1));
                bool xin1 = (x0 + 1.f >= 0.f) && (x0 + 1.f <= (float)(W - 1));
                bool yin0 = (y0       >= 0.f) && (y0       <= (float)(H - 1));
                bool yin1 = (y0 + 1.f >= 0.f) && (y0 + 1.f <= (float)(H - 1));

                int xi0 = (int)fminf(fmaxf(x0,       0.f), (float)(W - 1));
                int xi1 = (int)fminf(fmaxf(x0 + 1.f, 0.f), (float)(W - 1));
                int yi0 = (int)fminf(fmaxf(y0,       0.f), (float)(H - 1));
                int yi1 = (int)fminf(fmaxf(y0 + 1.f, 0.f), (float)(H - 1));

                float s = 0.f;
                if (xin0 && yin0) s += wx0 * wy0 * base[((size_t)yi0 * W + xi0) * CH + c];
                if (xin1 && yin0) s += wx1 * wy0 * base[((size_t)yi0 * W + xi1) * CH + c];
                if (xin0 && yin1) s += wx0 * wy1 * base[((size_t)yi1 * W + xi0) * CH + c];
                if (xin1 && yin1) s += wx1 * wy1 * base[((size_t)yi1 * W + xi1) * CH + c];
                acc += s;
            }
        }
        total += acc / fmaxf(cnt, 1.f);
    }
    g_ctx[(size_t)bq * CH + c] = total * 0.5f;
}

// ---------------------------------------------------------------------------
// Kernel 3: SGEMM  out[M,N] = A[M,K] @ W[N,K]^T + bias[N]
// 64x64 tile, 256 threads, 4x4 per-thread microtile.
// ---------------------------------------------------------------------------
__global__ __launch_bounds__(256) void gemm_atb_kernel(
    const float* __restrict__ A, const float* __restrict__ W,
    const float* __restrict__ bias, float* __restrict__ out,
    int M, int N, int K)
{
    __shared__ float As[16][68];
    __shared__ float Bs[16][68];

    int tm = blockIdx.y * 64;
    int tn = blockIdx.x * 64;
    int tid = threadIdx.x;
    int tx = tid & 15;
    int ty = tid >> 4;

    float acc[4][4] = {};

    for (int k0 = 0; k0 < K; k0 += 16) {
#pragma unroll
        for (int i = 0; i < 4; i++) {
            int idx = tid + i * 256;        // 0..1023
            int r   = idx >> 4;
            int kk  = idx & 15;
            int m = tm + r;
            As[kk][r] = (m < M) ? A[(size_t)m * K + k0 + kk] : 0.f;
            int n = tn + r;
            Bs[kk][r] = (n < N) ? W[(size_t)n * K + k0 + kk] : 0.f;
        }
        __syncthreads();
#pragma unroll
        for (int kk = 0; kk < 16; kk++) {
            float a[4], bb[4];
#pragma unroll
            for (int i = 0; i < 4; i++) a[i]  = As[kk][ty * 4 + i];
#pragma unroll
            for (int i = 0; i < 4; i++) bb[i] = Bs[kk][tx * 4 + i];
#pragma unroll
            for (int i = 0; i < 4; i++)
#pragma unroll
                for (int j = 0; j < 4; j++)
                    acc[i][j] += a[i] * bb[j];
        }
        __syncthreads();
    }

#pragma unroll
    for (int i = 0; i < 4; i++) {
        int m = tm + ty * 4 + i;
        if (m >= M) continue;
#pragma unroll
        for (int j = 0; j < 4; j++) {
            int n = tn + tx * 4 + j;
            out[(size_t)m * N + n] = acc[i][j] + bias[n];
        }
    }
}

// ---------------------------------------------------------------------------
// Kernel 4: fused attention (scores -> softmax -> AV) per (b,h,q) row
// grid (NQ, HEADS, BATCH), 256 threads
// ---------------------------------------------------------------------------
__global__ __launch_bounds__(256) void attn_kernel()
{
    int q = blockIdx.x;
    int h = blockIdx.y;
    int b = blockIdx.z;
    int tid = threadIdx.x;

    __shared__ float qv[HDIM];
    __shared__ float s[NQ];
    __shared__ float red0[8];
    __shared__ float red1[8];
    __shared__ float osum[8][HDIM];

    const size_t rowbase = ((size_t)(b * NQ + q)) * CH + h * HDIM;
    if (tid < HDIM) qv[tid] = g_qp[rowbase + tid];
    __syncthreads();

    const float scale = 0.1767766952966369f; // 1/sqrt(32)

    float m = -INFINITY;
    for (int j = tid; j < NQ; j += 256) {
        const float* krow = g_kp + ((size_t)(b * NQ + j)) * CH + h * HDIM;
        float acc = 0.f;
#pragma unroll
        for (int d = 0; d < HDIM; d += 4) {
            float4 kk = *(const float4*)(krow + d);
            acc += qv[d] * kk.x + qv[d + 1] * kk.y + qv[d + 2] * kk.z + qv[d + 3] * kk.w;
        }
        acc *= scale;
        s[j] = acc;
        m = fmaxf(m, acc);
    }
    // block max
#pragma unroll
    for (int off = 16; off; off >>= 1) m = fmaxf(m, __shfl_xor_sync(0xFFFFFFFFu, m, off));
    if ((tid & 31) == 0) red0[tid >> 5] = m;
    __syncthreads();
    m = red0[0];
#pragma unroll
    for (int i = 1; i < 8; i++) m = fmaxf(m, red0[i]);

    // exp + sum
    float lsum = 0.f;
    for (int j = tid; j < NQ; j += 256) {
        float e = __expf(s[j] - m);
        s[j] = e;
        lsum += e;
    }
#pragma unroll
    for (int off = 16; off; off >>= 1) lsum += __shfl_xor_sync(0xFFFFFFFFu, lsum, off);
    if ((tid & 31) == 0) red1[tid >> 5] = lsum;
    __syncthreads();
    float total = 0.f;
#pragma unroll
    for (int i = 0; i < 8; i++) total += red1[i];

    // AV: 8 groups of 32 threads, group g handles j = g, g+8, ...
    int g = tid >> 5;
    int d = tid & 31;
    float acc = 0.f;
    for (int j = g; j < NQ; j += 8) {
        acc += s[j] * g_vp[((size_t)(b * NQ + j)) * CH + h * HDIM + d];
    }
    osum[g][d] = acc;
    __syncthreads();
    if (tid < HDIM) {
        float o = 0.f;
#pragma unroll
        for (int gg = 0; gg < 8; gg++) o += osum[gg][tid];
        g_ao[rowbase + tid] = o / total;
    }
}

// ---------------------------------------------------------------------------
// Host launcher
// ---------------------------------------------------------------------------
extern "C" void kernel_launch(void* const* d_in, const int* in_sizes, int n_in,
                              void* d_out, int out_size)
{
    const float* f0   = (const float*)d_in[0];
    const float* f1   = (const float*)d_in[1];
    const float* refs = (const float*)d_in[2];
    const float* intr = (const float*)d_in[3];
    const float* extr = (const float*)d_in[4];
    const float* qin  = (const float*)d_in[5];
    const float* Wq   = (const float*)d_in[6];
    const float* bq   = (const float*)d_in[7];
    const float* Wk   = (const float*)d_in[8];
    const float* bk   = (const float*)d_in[9];
    const float* Wv   = (const float*)d_in[10];
    const float* bv   = (const float*)d_in[11];
    const float* Wo   = (const float*)d_in[12];
    const float* bo   = (const float*)d_in[13];
    float* out = (float*)d_out;

    float *p_ctx, *p_qp, *p_kp, *p_vp, *p_ao;
    cudaGetSymbolAddress((void**)&p_ctx, g_ctx);
    cudaGetSymbolAddress((void**)&p_qp,  g_qp);
    cudaGetSymbolAddress((void**)&p_kp,  g_kp);
    cudaGetSymbolAddress((void**)&p_vp,  g_vp);
    cudaGetSymbolAddress((void**)&p_ao,  g_ao);

    // 1. NHWC transposes
    {
        dim3 blk(32, 8);
        dim3 g0((H0 * W0) / 32, CH / 32, BATCH * VIEWS);
        transpose_nhwc_kernel<<<g0, blk>>>(f0, H0 * W0, 0);
        dim3 g1((H1 * W1) / 32, CH / 32, BATCH * VIEWS);
        transpose_nhwc_kernel<<<g1, blk>>>(f1, H1 * W1, 1);
    }

    // 2. Sampler -> g_ctx
    sampler_kernel<<<BATCH * NQ, CH>>>(refs, intr, extr);

    // 3. Projections
    const int M = BATCH * NQ;            // 1800
    dim3 gblk(256);
    dim3 ggrid(CH / 64, (M + 63) / 64);  // (4, 29)
    gemm_atb_kernel<<<ggrid, gblk>>>(qin,   Wq, bq, p_qp, M, CH, CH);
    gemm_atb_kernel<<<ggrid, gblk>>>(p_ctx, Wk, bk, p_kp, M, CH, CH);
    gemm_atb_kernel<<<ggrid, gblk>>>(p_ctx, Wv, bv, p_vp, M, CH, CH);

    // 4. Attention
    attn_kernel<<<dim3(NQ, HEADS, BATCH), 256>>>();

    // 5. Output projection -> d_out
    gemm_atb_kernel<<<ggrid, gblk>>>(p_ao, Wo, bo, out, M, CH, CH);
}

// round 3
// speedup vs baseline: 2.1949x; 2.1949x over previous
#include <cuda_runtime.h>
#include <math.h>

// ---------------------------------------------------------------------------
// Problem constants
// ---------------------------------------------------------------------------
#define BATCH 2
#define VIEWS 6
#define CH    256
#define NQ    900
#define KKP   4
#define H0    64
#define W0    176
#define H1    32
#define W1    88
#define HEADS 8
#define HDIM  32

// ---------------------------------------------------------------------------
// Device scratch
// ---------------------------------------------------------------------------
__device__ float g_feat0[(size_t)BATCH * VIEWS * H0 * W0 * CH]; // NHWC level 0
__device__ float g_feat1[(size_t)BATCH * VIEWS * H1 * W1 * CH]; // NHWC level 1
__device__ float g_ctx[BATCH * NQ * CH];
__device__ float g_qp [BATCH * NQ * CH];
__device__ float g_kp [BATCH * NQ * CH];
__device__ float g_vp [BATCH * NQ * CH];
__device__ float g_ao [BATCH * NQ * CH];

// ---------------------------------------------------------------------------
// Kernel 1: CHW -> HWC transpose
// ---------------------------------------------------------------------------
__global__ void transpose_nhwc_kernel(const float* __restrict__ in, int HW, int level) {
    __shared__ float tile[32][33];
    float* out = level ? g_feat1 : g_feat0;
    int bv = blockIdx.z;
    int c0 = blockIdx.y * 32;
    int p0 = blockIdx.x * 32;
    const float* inp = in  + (size_t)bv * CH * HW;
    float*      outp = out + (size_t)bv * HW * CH;

#pragma unroll
    for (int i = 0; i < 32; i += 8) {
        int c = c0 + threadIdx.y + i;
        int p = p0 + threadIdx.x;
        float v = (p < HW) ? inp[(size_t)c * HW + p] : 0.f;
        tile[threadIdx.y + i][threadIdx.x] = v;
    }
    __syncthreads();
#pragma unroll
    for (int i = 0; i < 32; i += 8) {
        int p = p0 + threadIdx.y + i;
        int c = c0 + threadIdx.x;
        if (p < HW) outp[(size_t)p * CH + c] = tile[threadIdx.x][threadIdx.y + i];
    }
}

// ---------------------------------------------------------------------------
// Kernel 2: multi-view multi-level sampler -> g_ctx[B,Q,C]
// ---------------------------------------------------------------------------
__global__ __launch_bounds__(256) void sampler_kernel(
    const float* __restrict__ refs,
    const float* __restrict__ intr,
    const float* __restrict__ extr)
{
    int bq = blockIdx.x;
    int b  = bq / NQ;
    int c  = threadIdx.x;

    float rx = refs[bq * 3 + 0];
    float ry = refs[bq * 3 + 1];
    float rz = refs[bq * 3 + 2];

    const float kpx[KKP] = {0.f, 2.f, 0.f, -2.f};
    const float kpy[KKP] = {0.f, 0.f, 2.f, 0.f};

    float total = 0.f;

#pragma unroll
    for (int lev = 0; lev < 2; lev++) {
        const float* fm = lev ? g_feat1 : g_feat0;
        const int H = lev ? H1 : H0;
        const int W = lev ? W1 : W0;

        float acc = 0.f;
        float cnt = 0.f;

        for (int v = 0; v < VIEWS; v++) {
            const float* E  = extr + (size_t)(b * VIEWS + v) * 16;
            const float* Km = intr + (size_t)(b * VIEWS + v) * 9;
            const float* base = fm + (size_t)(b * VIEWS + v) * H * W * CH;

#pragma unroll
            for (int k = 0; k < KKP; k++) {
                float px = rx + kpx[k];
                float py = ry + kpy[k];
                float pz = rz;
                float cxx = E[0]*px + E[1]*py + E[2]*pz  + E[3];
                float cyy = E[4]*px + E[5]*py + E[6]*pz  + E[7];
                float czz = E[8]*px + E[9]*py + E[10]*pz + E[11];
                float u  = Km[0]*cxx + Km[1]*cyy + Km[2]*czz;
                float vv = Km[3]*cxx + Km[4]*cyy + Km[5]*czz;
                float w  = Km[6]*cxx + Km[7]*cyy + Km[8]*czz;

                bool valid = (w > 0.f);
                if (valid) cnt += 1.f;
                if (!valid) continue;

                float zs = (fabsf(w) > 1e-6f) ? w : 1e-6f;
                float x = u / zs;
                float y = vv / zs;

                float x0 = floorf(x), y0 = floorf(y);
                float wx1 = x - x0, wx0 = 1.f - wx1;
                float wy1 = y - y0, wy0 = 1.f - wy1;

                bool xin0 = (x0       >= 0.f) && (x0       <= (float)(W - 1));
                bool xin1 = (x0 + 1.f >= 0.f) && (x0 + 1.f <= (float)(W - 1));
                bool yin0 = (y0       >= 0.f) && (y0       <= (float)(H - 1));
                bool yin1 = (y0 + 1.f >= 0.f) && (y0 + 1.f <= (float)(H - 1));

                int xi0 = (int)fminf(fmaxf(x0,       0.f), (float)(W - 1));
                int xi1 = (int)fminf(fmaxf(x0 + 1.f, 0.f), (float)(W - 1));
                int yi0 = (int)fminf(fmaxf(y0,       0.f), (float)(H - 1));
                int yi1 = (int)fminf(fmaxf(y0 + 1.f, 0.f), (float)(H - 1));

                float s = 0.f;
                if (xin0 && yin0) s += wx0 * wy0 * base[((size_t)yi0 * W + xi0) * CH + c];
                if (xin1 && yin0) s += wx1 * wy0 * base[((size_t)yi0 * W + xi1) * CH + c];
                if (xin0 && yin1) s += wx0 * wy1 * base[((size_t)yi1 * W + xi0) * CH + c];
                if (xin1 && yin1) s += wx1 * wy1 * base[((size_t)yi1 * W + xi1) * CH + c];
                acc += s;
            }
        }
        total += acc / fmaxf(cnt, 1.f);
    }
    g_ctx[(size_t)bq * CH + c] = total * 0.5f;
}

// ---------------------------------------------------------------------------
// SGEMM body: out[M,256] = A[M,256] @ W[256,256]^T + bias
// 64x64 tile, 256 threads, 4x4 microtile, float4 smem reads.
// ---------------------------------------------------------------------------
__device__ __forceinline__ void gemm_body(
    const float* __restrict__ A, const float* __restrict__ W,
    const float* __restrict__ bias, float* __restrict__ out, int M)
{
    const int K = 256, N = 256;
    __shared__ float As[16][68];
    __shared__ float Bs[16][68];

    int tm = blockIdx.y * 64;
    int tn = blockIdx.x * 64;
    int tid = threadIdx.x;
    int tx = tid & 15;
    int ty = tid >> 4;

    float acc[4][4] = {};

    for (int k0 = 0; k0 < K; k0 += 16) {
#pragma unroll
        for (int i = 0; i < 4; i++) {
            int idx = tid + i * 256;
            int r   = idx >> 4;
            int kk  = idx & 15;
            int m = tm + r;
            As[kk][r] = (m < M) ? A[(size_t)m * K + k0 + kk] : 0.f;
            int n = tn + r;
            Bs[kk][r] = W[(size_t)n * K + k0 + kk];
        }
        __syncthreads();
#pragma unroll
        for (int kk = 0; kk < 16; kk++) {
            float4 a4 = *(const float4*)&As[kk][ty * 4];
            float4 b4 = *(const float4*)&Bs[kk][tx * 4];
            float a[4] = {a4.x, a4.y, a4.z, a4.w};
            float bb[4] = {b4.x, b4.y, b4.z, b4.w};
#pragma unroll
            for (int i = 0; i < 4; i++)
#pragma unroll
                for (int j = 0; j < 4; j++)
                    acc[i][j] += a[i] * bb[j];
        }
        __syncthreads();
    }

#pragma unroll
    for (int i = 0; i < 4; i++) {
        int m = tm + ty * 4 + i;
        if (m >= M) continue;
#pragma unroll
        for (int j = 0; j < 4; j++) {
            int n = tn + tx * 4 + j;
            out[(size_t)m * N + n] = acc[i][j] + bias[n];
        }
    }
}

// Fused QKV projection: blockIdx.z selects which GEMM.
__global__ __launch_bounds__(256) void gemm_qkv_kernel(
    const float* __restrict__ qin,
    const float* __restrict__ Wq, const float* __restrict__ bq,
    const float* __restrict__ Wk, const float* __restrict__ bk,
    const float* __restrict__ Wv, const float* __restrict__ bv,
    int M)
{
    int which = blockIdx.z;
    const float* A = (which == 0) ? qin : g_ctx;
    const float* W = (which == 0) ? Wq : ((which == 1) ? Wk : Wv);
    const float* b = (which == 0) ? bq : ((which == 1) ? bk : bv);
    float* out     = (which == 0) ? g_qp : ((which == 1) ? g_kp : g_vp);
    gemm_body(A, W, b, out, M);
}

__global__ __launch_bounds__(256) void gemm_o_kernel(
    const float* __restrict__ Wo, const float* __restrict__ bo,
    float* __restrict__ out, int M)
{
    gemm_body(g_ao, Wo, bo, out, M);
}

// ---------------------------------------------------------------------------
// Kernel 4: flash-style tiled attention
// block = (b, h, 32-query tile), 256 threads, K/V streamed in 64-key tiles.
// ---------------------------------------------------------------------------
#define TQ 32
#define TK 64
#define QS_S 36
#define KS_S 36
#define SS_S 68

__global__ __launch_bounds__(256) void attn_kernel()
{
    int q0 = blockIdx.x * TQ;
    int h  = blockIdx.y;
    int b  = blockIdx.z;
    int tid = threadIdx.x;

    __shared__ float Qs[TQ * QS_S];
    __shared__ float Ks[TK * KS_S];
    __shared__ float Vs[TK * KS_S];
    __shared__ float Ss[TQ * SS_S];
    __shared__ float ms[TQ], ls[TQ], al[TQ];

    const float scale = 0.1767766952966369f; // 1/sqrt(32)
    const float NEG_INF = -1e30f;

    // load Q tile (zero-fill out-of-range queries)
    {
        int row = tid >> 3;
        int c4  = (tid & 7) * 4;
        int gq  = q0 + row;
        float4 v = make_float4(0.f, 0.f, 0.f, 0.f);
        if (gq < NQ)
            v = *(const float4*)&g_qp[((size_t)(b * NQ + gq)) * CH + h * HDIM + c4];
        Qs[row * QS_S + c4 + 0] = v.x;
        Qs[row * QS_S + c4 + 1] = v.y;
        Qs[row * QS_S + c4 + 2] = v.z;
        Qs[row * QS_S + c4 + 3] = v.w;
    }
    if (tid < TQ) { ms[tid] = NEG_INF; ls[tid] = 0.f; }

    float o[4] = {0.f, 0.f, 0.f, 0.f};
    int g = tid >> 5;   // warp id = query group (4 queries each)
    int d = tid & 31;   // head dim

    const int NTILES = (NQ + TK - 1) / TK;  // 15

    for (int kt = 0; kt < NTILES; kt++) {
        int k0 = kt * TK;
        __syncthreads();
        // load K/V tiles: 64 rows x 8 float4 = 512 float4 -> 2 per thread
#pragma unroll
        for (int i = 0; i < 2; i++) {
            int idx = tid + i * 256;
            int row = idx >> 3;
            int c4  = (idx & 7) * 4;
            int gk  = k0 + row;
            float4 kv = make_float4(0.f, 0.f, 0.f, 0.f);
            float4 vv = make_float4(0.f, 0.f, 0.f, 0.f);
            if (gk < NQ) {
                size_t base = ((size_t)(b * NQ + gk)) * CH + h * HDIM + c4;
                kv = *(const float4*)&g_kp[base];
                vv = *(const float4*)&g_vp[base];
            }
            int so = row * KS_S + c4;
            Ks[so + 0] = kv.x; Ks[so + 1] = kv.y; Ks[so + 2] = kv.z; Ks[so + 3] = kv.w;
            Vs[so + 0] = vv.x; Vs[so + 1] = vv.y; Vs[so + 2] = vv.z; Vs[so + 3] = vv.w;
        }
        __syncthreads();

        // Phase A: scores. thread: one query (tid>>3), 8 keys strided by 8.
        {
            int qa = tid >> 3;
            int kb = tid & 7;
            float acc[8] = {0.f, 0.f, 0.f, 0.f, 0.f, 0.f, 0.f, 0.f};
#pragma unroll
            for (int dd = 0; dd < HDIM; dd += 4) {
                float4 qv = *(const float4*)&Qs[qa * QS_S + dd];
#pragma unroll
                for (int i = 0; i < 8; i++) {
                    float4 kv = *(const float4*)&Ks[(kb + 8 * i) * KS_S + dd];
                    acc[i] += qv.x * kv.x + qv.y * kv.y + qv.z * kv.z + qv.w * kv.w;
                }
            }
#pragma unroll
            for (int i = 0; i < 8; i++) {
                int kk = kb + 8 * i;
                float s = acc[i] * scale;
                if (k0 + kk >= NQ) s = NEG_INF;
                Ss[qa * SS_S + kk] = s;
            }
        }
        __syncthreads();

        // Phase B: online softmax update. row = tid>>3, 8 threads/row.
        {
            int row = tid >> 3;
            int sub = tid & 7;
            float* srow = &Ss[row * SS_S + sub * 8];
            float4 s0 = *(float4*)&srow[0];
            float4 s1 = *(float4*)&srow[4];
            float lm = fmaxf(fmaxf(fmaxf(s0.x, s0.y), fmaxf(s0.z, s0.w)),
                             fmaxf(fmaxf(s1.x, s1.y), fmaxf(s1.z, s1.w)));
#pragma unroll
            for (int off = 1; off < 8; off <<= 1)
                lm = fmaxf(lm, __shfl_xor_sync(0xFFFFFFFFu, lm, off));
            float m_old = ms[row];
            float m_new = fmaxf(m_old, lm);
            float alpha = __expf(m_old - m_new);
            float p0 = __expf(s0.x - m_new), p1 = __expf(s0.y - m_new);
            float p2 = __expf(s0.z - m_new), p3 = __expf(s0.w - m_new);
            float p4 = __expf(s1.x - m_new), p5 = __expf(s1.y - m_new);
            float p6 = __expf(s1.z - m_new), p7 = __expf(s1.w - m_new);
            *(float4*)&srow[0] = make_float4(p0, p1, p2, p3);
            *(float4*)&srow[4] = make_float4(p4, p5, p6, p7);
            float lsum = p0 + p1 + p2 + p3 + p4 + p5 + p6 + p7;
#pragma unroll
            for (int off = 1; off < 8; off <<= 1)
                lsum += __shfl_xor_sync(0xFFFFFFFFu, lsum, off);
            if (sub == 0) {
                ms[row] = m_new;
                ls[row] = ls[row] * alpha + lsum;
                al[row] = alpha;
            }
        }
        __syncthreads();

        // Phase C: O accumulate. warp g handles queries g*4..g*4+3, lane = dim d.
        {
            float a0 = al[g * 4 + 0], a1 = al[g * 4 + 1];
            float a2 = al[g * 4 + 2], a3 = al[g * 4 + 3];
            o[0] *= a0; o[1] *= a1; o[2] *= a2; o[3] *= a3;
#pragma unroll 4
            for (int k = 0; k < TK; k += 4) {
                float v0 = Vs[(k + 0) * KS_S + d];
                float v1 = Vs[(k + 1) * KS_S + d];
                float v2 = Vs[(k + 2) * KS_S + d];
                float v3 = Vs[(k + 3) * KS_S + d];
#pragma unroll
                for (int j = 0; j < 4; j++) {
                    float4 p = *(const float4*)&Ss[(g * 4 + j) * SS_S + k];
                    o[j] += p.x * v0 + p.y * v1 + p.z * v2 + p.w * v3;
                }
            }
        }
    }
    __syncthreads();

#pragma unroll
    for (int j = 0; j < 4; j++) {
        int q = g * 4 + j;
        int gq = q0 + q;
        if (gq < NQ)
            g_ao[((size_t)(b * NQ + gq)) * CH + h * HDIM + d] = o[j] / ls[q];
    }
}

// ---------------------------------------------------------------------------
// Host launcher
// ---------------------------------------------------------------------------
extern "C" void kernel_launch(void* const* d_in, const int* in_sizes, int n_in,
                              void* d_out, int out_size)
{
    const float* f0   = (const float*)d_in[0];
    const float* f1   = (const float*)d_in[1];
    const float* refs = (const float*)d_in[2];
    const float* intr = (const float*)d_in[3];
    const float* extr = (const float*)d_in[4];
    const float* qin  = (const float*)d_in[5];
    const float* Wq   = (const float*)d_in[6];
    const float* bq   = (const float*)d_in[7];
    const float* Wk   = (const float*)d_in[8];
    const float* bk   = (const float*)d_in[9];
    const float* Wv   = (const float*)d_in[10];
    const float* bv   = (const float*)d_in[11];
    const float* Wo   = (const float*)d_in[12];
    const float* bo   = (const float*)d_in[13];
    float* out = (float*)d_out;

    // 1. NHWC transposes
    {
        dim3 blk(32, 8);
        dim3 g0((H0 * W0) / 32, CH / 32, BATCH * VIEWS);
        transpose_nhwc_kernel<<<g0, blk>>>(f0, H0 * W0, 0);
        dim3 g1((H1 * W1) / 32, CH / 32, BATCH * VIEWS);
        transpose_nhwc_kernel<<<g1, blk>>>(f1, H1 * W1, 1);
    }

    // 2. Sampler -> g_ctx
    sampler_kernel<<<BATCH * NQ, CH>>>(refs, intr, extr);

    // 3. Fused QKV projections
    const int M = BATCH * NQ;  // 1800
    {
        dim3 ggrid(CH / 64, (M + 63) / 64, 3);
        gemm_qkv_kernel<<<ggrid, 256>>>(qin, Wq, bq, Wk, bk, Wv, bv, M);
    }

    // 4. Attention
    attn_kernel<<<dim3((NQ + TQ - 1) / TQ, HEADS, BATCH), 256>>>();

    // 5. Output projection -> d_out
    {
        dim3 ggrid(CH / 64, (M + 63) / 64);
        gemm_o_kernel<<<ggrid, 256>>>(Wo, bo, out, M);
    }
}

// round 4
// speedup vs baseline: 2.7280x; 1.2429x over previous
#include <cuda_runtime.h>
#include <math.h>

// ---------------------------------------------------------------------------
// Problem constants
// ---------------------------------------------------------------------------
#define BATCH 2
#define VIEWS 6
#define CH    256
#define NQ    900
#define KKP   4
#define H0    64
#define W0    176
#define H1    32
#define W1    88
#define HEADS 8
#define HDIM  32

// ---------------------------------------------------------------------------
// Device scratch
// ---------------------------------------------------------------------------
__device__ float g_feat0[(size_t)BATCH * VIEWS * H0 * W0 * CH]; // NHWC level 0
__device__ float g_feat1[(size_t)BATCH * VIEWS * H1 * W1 * CH]; // NHWC level 1
__device__ float g_ctx[BATCH * NQ * CH];
__device__ float g_qp [BATCH * NQ * CH];
__device__ float g_kp [BATCH * NQ * CH];
__device__ float g_vp [BATCH * NQ * CH];
__device__ float g_ao [BATCH * NQ * CH];

// ---------------------------------------------------------------------------
// Kernel 1: CHW -> HWC transpose
// ---------------------------------------------------------------------------
__global__ void transpose_nhwc_kernel(const float* __restrict__ in, int HW, int level) {
    __shared__ float tile[32][33];
    float* out = level ? g_feat1 : g_feat0;
    int bv = blockIdx.z;
    int c0 = blockIdx.y * 32;
    int p0 = blockIdx.x * 32;
    const float* inp = in  + (size_t)bv * CH * HW;
    float*      outp = out + (size_t)bv * HW * CH;

#pragma unroll
    for (int i = 0; i < 32; i += 8) {
        int c = c0 + threadIdx.y + i;
        int p = p0 + threadIdx.x;
        float v = (p < HW) ? inp[(size_t)c * HW + p] : 0.f;
        tile[threadIdx.y + i][threadIdx.x] = v;
    }
    __syncthreads();
#pragma unroll
    for (int i = 0; i < 32; i += 8) {
        int p = p0 + threadIdx.y + i;
        int c = c0 + threadIdx.x;
        if (p < HW) outp[(size_t)p * CH + c] = tile[threadIdx.x][threadIdx.y + i];
    }
}

// ---------------------------------------------------------------------------
// Kernel 2: multi-view multi-level sampler -> g_ctx[B,Q,C]
// ---------------------------------------------------------------------------
__global__ __launch_bounds__(256) void sampler_kernel(
    const float* __restrict__ refs,
    const float* __restrict__ intr,
    const float* __restrict__ extr)
{
    int bq = blockIdx.x;
    int b  = bq / NQ;
    int c  = threadIdx.x;

    float rx = refs[bq * 3 + 0];
    float ry = refs[bq * 3 + 1];
    float rz = refs[bq * 3 + 2];

    const float kpx[KKP] = {0.f, 2.f, 0.f, -2.f};
    const float kpy[KKP] = {0.f, 0.f, 2.f, 0.f};

    float total = 0.f;

#pragma unroll
    for (int lev = 0; lev < 2; lev++) {
        const float* fm = lev ? g_feat1 : g_feat0;
        const int H = lev ? H1 : H0;
        const int W = lev ? W1 : W0;

        float acc = 0.f;
        float cnt = 0.f;

        for (int v = 0; v < VIEWS; v++) {
            const float* E  = extr + (size_t)(b * VIEWS + v) * 16;
            const float* Km = intr + (size_t)(b * VIEWS + v) * 9;
            const float* base = fm + (size_t)(b * VIEWS + v) * H * W * CH;

#pragma unroll
            for (int k = 0; k < KKP; k++) {
                float px = rx + kpx[k];
                float py = ry + kpy[k];
                float pz = rz;
                float cxx = E[0]*px + E[1]*py + E[2]*pz  + E[3];
                float cyy = E[4]*px + E[5]*py + E[6]*pz  + E[7];
                float czz = E[8]*px + E[9]*py + E[10]*pz + E[11];
                float u  = Km[0]*cxx + Km[1]*cyy + Km[2]*czz;
                float vv = Km[3]*cxx + Km[4]*cyy + Km[5]*czz;
                float w  = Km[6]*cxx + Km[7]*cyy + Km[8]*czz;

                bool valid = (w > 0.f);
                if (valid) cnt += 1.f;
                if (!valid) continue;

                float zs = (fabsf(w) > 1e-6f) ? w : 1e-6f;
                float x = u / zs;
                float y = vv / zs;

                float x0 = floorf(x), y0 = floorf(y);
                float wx1 = x - x0, wx0 = 1.f - wx1;
                float wy1 = y - y0, wy0 = 1.f - wy1;

                bool xin0 = (x0       >= 0.f) && (x0       <= (float)(W - 1));
                bool xin1 = (x0 + 1.f >= 0.f) && (x0 + 1.f <= (float)(W - 1));
                bool yin0 = (y0       >= 0.f) && (y0       <= (float)(H - 1));
                bool yin1 = (y0 + 1.f >= 0.f) && (y0 + 1.f <= (float)(H - 1));

                int xi0 = (int)fminf(fmaxf(x0,       0.f), (float)(W - 1));
                int xi1 = (int)fminf(fmaxf(x0 + 1.f, 0.f), (float)(W - 1));
                int yi0 = (int)fminf(fmaxf(y0,       0.f), (float)(H - 1));
                int yi1 = (int)fminf(fmaxf(y0 + 1.f, 0.f), (float)(H - 1));

                float s = 0.f;
                if (xin0 && yin0) s += wx0 * wy0 * base[((size_t)yi0 * W + xi0) * CH + c];
                if (xin1 && yin0) s += wx1 * wy0 * base[((size_t)yi0 * W + xi1) * CH + c];
                if (xin0 && yin1) s += wx0 * wy1 * base[((size_t)yi1 * W + xi0) * CH + c];
                if (xin1 && yin1) s += wx1 * wy1 * base[((size_t)yi1 * W + xi1) * CH + c];
                acc += s;
            }
        }
        total += acc / fmaxf(cnt, 1.f);
    }
    g_ctx[(size_t)bq * CH + c] = total * 0.5f;
}

// ---------------------------------------------------------------------------
// SGEMM body: out[M,256] = A[M,256] @ W[256,256]^T + bias
// ---------------------------------------------------------------------------
__device__ __forceinline__ void gemm_body(
    const float* __restrict__ A, const float* __restrict__ W,
    const float* __restrict__ bias, float* __restrict__ out, int M)
{
    const int K = 256, N = 256;
    __shared__ float As[16][68];
    __shared__ float Bs[16][68];

    int tm = blockIdx.y * 64;
    int tn = blockIdx.x * 64;
    int tid = threadIdx.x;
    int tx = tid & 15;
    int ty = tid >> 4;

    float acc[4][4] = {};

    for (int k0 = 0; k0 < K; k0 += 16) {
#pragma unroll
        for (int i = 0; i < 4; i++) {
            int idx = tid + i * 256;
            int r   = idx >> 4;
            int kk  = idx & 15;
            int m = tm + r;
            As[kk][r] = (m < M) ? A[(size_t)m * K + k0 + kk] : 0.f;
            int n = tn + r;
            Bs[kk][r] = W[(size_t)n * K + k0 + kk];
        }
        __syncthreads();
#pragma unroll
        for (int kk = 0; kk < 16; kk++) {
            float4 a4 = *(const float4*)&As[kk][ty * 4];
            float4 b4 = *(const float4*)&Bs[kk][tx * 4];
            float a[4] = {a4.x, a4.y, a4.z, a4.w};
            float bb[4] = {b4.x, b4.y, b4.z, b4.w};
#pragma unroll
            for (int i = 0; i < 4; i++)
#pragma unroll
                for (int j = 0; j < 4; j++)
                    acc[i][j] += a[i] * bb[j];
        }
        __syncthreads();
    }

#pragma unroll
    for (int i = 0; i < 4; i++) {
        int m = tm + ty * 4 + i;
        if (m >= M) continue;
#pragma unroll
        for (int j = 0; j < 4; j++) {
            int n = tn + tx * 4 + j;
            out[(size_t)m * N + n] = acc[i][j] + bias[n];
        }
    }
}

__global__ __launch_bounds__(256) void gemm_qkv_kernel(
    const float* __restrict__ qin,
    const float* __restrict__ Wq, const float* __restrict__ bq,
    const float* __restrict__ Wk, const float* __restrict__ bk,
    const float* __restrict__ Wv, const float* __restrict__ bv,
    int M)
{
    int which = blockIdx.z;
    const float* A = (which == 0) ? qin : g_ctx;
    const float* W = (which == 0) ? Wq : ((which == 1) ? Wk : Wv);
    const float* b = (which == 0) ? bq : ((which == 1) ? bk : bv);
    float* out     = (which == 0) ? g_qp : ((which == 1) ? g_kp : g_vp);
    gemm_body(A, W, b, out, M);
}

__global__ __launch_bounds__(256) void gemm_o_kernel(
    const float* __restrict__ Wo, const float* __restrict__ bo,
    float* __restrict__ out, int M)
{
    gemm_body(g_ao, Wo, bo, out, M);
}

// ---------------------------------------------------------------------------
// Kernel 4: register-blocked flash attention
// block = (b, h, 64-query tile), 256 threads.
// Q/K stored d-major in smem; 64x64 score tile via 4x4 outer-product microtile;
// AV via 2-way k-split outer product. P kept in smem between phases.
// ---------------------------------------------------------------------------
#define ATQ 64
#define ATK 64
#define QT_S 68   // Qt/Kt row stride (d-major: [32][QT_S])
#define PS_S 68   // P row stride
#define VS_S 36   // V row stride

__global__ __launch_bounds__(256) void attn_kernel()
{
    const int q0 = blockIdx.x * ATQ;
    const int h  = blockIdx.y;
    const int b  = blockIdx.z;
    const int tid = threadIdx.x;

    __shared__ float Qt[HDIM][QT_S];
    __shared__ float Kt[HDIM][QT_S];
    __shared__ float Vs[ATK][VS_S];
    __shared__ float Ps[ATQ][PS_S];
    __shared__ float ms[ATQ], ls[ATQ], al[ATQ];

    const float scale = 0.1767766952966369f; // 1/sqrt(32)

    // ---- load Q tile transposed (d-major) ----
    {
        int q  = tid >> 2;
        int dg = (tid & 3) * 8;
        int gq = q0 + q;
        float4 v0 = make_float4(0.f, 0.f, 0.f, 0.f);
        float4 v1 = make_float4(0.f, 0.f, 0.f, 0.f);
        if (gq < NQ) {
            const float* p = &g_qp[((size_t)(b * NQ + gq)) * CH + h * HDIM + dg];
            v0 = *(const float4*)p;
            v1 = *(const float4*)(p + 4);
        }
        Qt[dg + 0][q] = v0.x; Qt[dg + 1][q] = v0.y;
        Qt[dg + 2][q] = v0.z; Qt[dg + 3][q] = v0.w;
        Qt[dg + 4][q] = v1.x; Qt[dg + 5][q] = v1.y;
        Qt[dg + 6][q] = v1.z; Qt[dg + 7][q] = v1.w;
    }
    if (tid < ATQ) { ms[tid] = -1e30f; ls[tid] = 0.f; }

    // phase-A thread mapping
    const int ia = tid >> 4;     // q-group 0..15
    const int ja = tid & 15;     // k-group 0..15
    // phase-C thread mapping
    const int ks = tid >> 7;     // k-split 0/1
    const int rc = tid & 127;
    const int ic = rc >> 3;      // q-group 0..15
    const int jd = rc & 7;       // d-group 0..7

    float o[4][4] = {};

    const int NTILES = (NQ + ATK - 1) / ATK;  // 15

    for (int kt = 0; kt < NTILES; kt++) {
        const int k0 = kt * ATK;
        __syncthreads();

        // ---- load K transposed + V straight ----
        {
            int k  = tid >> 2;
            int dg = (tid & 3) * 8;
            int gk = k0 + k;
            float4 a0 = make_float4(0.f, 0.f, 0.f, 0.f);
            float4 a1 = make_float4(0.f, 0.f, 0.f, 0.f);
            float4 w0 = make_float4(0.f, 0.f, 0.f, 0.f);
            float4 w1 = make_float4(0.f, 0.f, 0.f, 0.f);
            if (gk < NQ) {
                size_t base = ((size_t)(b * NQ + gk)) * CH + h * HDIM + dg;
                a0 = *(const float4*)&g_kp[base];
                a1 = *(const float4*)&g_kp[base + 4];
                w0 = *(const float4*)&g_vp[base];
                w1 = *(const float4*)&g_vp[base + 4];
            }
            Kt[dg + 0][k] = a0.x; Kt[dg + 1][k] = a0.y;
            Kt[dg + 2][k] = a0.z; Kt[dg + 3][k] = a0.w;
            Kt[dg + 4][k] = a1.x; Kt[dg + 5][k] = a1.y;
            Kt[dg + 6][k] = a1.z; Kt[dg + 7][k] = a1.w;
            *(float4*)&Vs[k][dg]     = w0;
            *(float4*)&Vs[k][dg + 4] = w1;
        }
        __syncthreads();

        // ---- phase A: 64x64 scores, 4x4 microtile ----
        {
            float acc[4][4] = {};
#pragma unroll
            for (int dd = 0; dd < HDIM; dd++) {
                float4 a4 = *(const float4*)&Qt[dd][ia * 4];
                float4 b4 = *(const float4*)&Kt[dd][ja * 4];
                float av[4] = {a4.x, a4.y, a4.z, a4.w};
                float bv[4] = {b4.x, b4.y, b4.z, b4.w};
#pragma unroll
                for (int a = 0; a < 4; a++)
#pragma unroll
                    for (int c = 0; c < 4; c++)
                        acc[a][c] += av[a] * bv[c];
            }
            // scale + key mask
#pragma unroll
            for (int c = 0; c < 4; c++) {
                bool inb = (k0 + ja * 4 + c) < NQ;
#pragma unroll
                for (int a = 0; a < 4; a++)
                    acc[a][c] = inb ? acc[a][c] * scale : -1e30f;
            }
            // per-row max (reduce across 16 ja lanes), combine with running max
            float mn[4], mo[4];
#pragma unroll
            for (int a = 0; a < 4; a++) {
                float rm = fmaxf(fmaxf(acc[a][0], acc[a][1]),
                                 fmaxf(acc[a][2], acc[a][3]));
#pragma unroll
                for (int off = 1; off < 16; off <<= 1)
                    rm = fmaxf(rm, __shfl_xor_sync(0xFFFFFFFFu, rm, off));
                mo[a] = ms[ia * 4 + a];
                mn[a] = fmaxf(mo[a], rm);
            }
            // exponentials + row sums
            float rs[4];
#pragma unroll
            for (int a = 0; a < 4; a++) {
                float s = 0.f;
#pragma unroll
                for (int c = 0; c < 4; c++) {
                    float p = __expf(acc[a][c] - mn[a]);
                    acc[a][c] = p;
                    s += p;
                }
#pragma unroll
                for (int off = 1; off < 16; off <<= 1)
                    s += __shfl_xor_sync(0xFFFFFFFFu, s, off);
                rs[a] = s;
            }
            if (ja == 0) {
#pragma unroll
                for (int a = 0; a < 4; a++) {
                    int row = ia * 4 + a;
                    float alpha = __expf(mo[a] - mn[a]);
                    al[row] = alpha;
                    ms[row] = mn[a];
                    ls[row] = ls[row] * alpha + rs[a];
                }
            }
            // store P
#pragma unroll
            for (int a = 0; a < 4; a++) {
                float4 p4 = make_float4(acc[a][0], acc[a][1], acc[a][2], acc[a][3]);
                *(float4*)&Ps[ia * 4 + a][ja * 4] = p4;
            }
        }
        __syncthreads();

        // ---- phase C: O += P * V, 2-way k-split, 4x4 microtile ----
        {
#pragma unroll
            for (int a = 0; a < 4; a++) {
                float alpha = al[ic * 4 + a];
                o[a][0] *= alpha; o[a][1] *= alpha;
                o[a][2] *= alpha; o[a][3] *= alpha;
            }
            const int kb = ks * 32;
#pragma unroll 8
            for (int k = 0; k < 32; k += 2) {
                float4 v0 = *(const float4*)&Vs[kb + k][jd * 4];
                float4 v1 = *(const float4*)&Vs[kb + k + 1][jd * 4];
#pragma unroll
                for (int a = 0; a < 4; a++) {
                    float2 p = *(const float2*)&Ps[ic * 4 + a][kb + k];
                    o[a][0] += p.x * v0.x + p.y * v1.x;
                    o[a][1] += p.x * v0.y + p.y * v1.y;
                    o[a][2] += p.x * v0.z + p.y * v1.z;
                    o[a][3] += p.x * v0.w + p.y * v1.w;
                }
            }
        }
    }

    // ---- combine k-splits via Ps scratch, then write out ----
    __syncthreads();
    if (ks == 0) {
#pragma unroll
        for (int a = 0; a < 4; a++)
            *(float4*)&Ps[ic * 4 + a][jd * 4] =
                make_float4(o[a][0], o[a][1], o[a][2], o[a][3]);
    }
    __syncthreads();
    if (ks == 1) {
#pragma unroll
        for (int a = 0; a < 4; a++) {
            float4 t = *(float4*)&Ps[ic * 4 + a][jd * 4];
            t.x += o[a][0]; t.y += o[a][1]; t.z += o[a][2]; t.w += o[a][3];
            *(float4*)&Ps[ic * 4 + a][jd * 4] = t;
        }
    }
    __syncthreads();
    {
        int q  = tid >> 2;
        int dg = (tid & 3) * 8;
        int gq = q0 + q;
        if (gq < NQ) {
            float inv = 1.f / ls[q];
            float4 r0 = *(const float4*)&Ps[q][dg];
            float4 r1 = *(const float4*)&Ps[q][dg + 4];
            r0.x *= inv; r0.y *= inv; r0.z *= inv; r0.w *= inv;
            r1.x *= inv; r1.y *= inv; r1.z *= inv; r1.w *= inv;
            float* dst = &g_ao[((size_t)(b * NQ + gq)) * CH + h * HDIM + dg];
            *(float4*)dst       = r0;
            *(float4*)(dst + 4) = r1;
        }
    }
}

// ---------------------------------------------------------------------------
// Host launcher
// ---------------------------------------------------------------------------
extern "C" void kernel_launch(void* const* d_in, const int* in_sizes, int n_in,
                              void* d_out, int out_size)
{
    const float* f0   = (const float*)d_in[0];
    const float* f1   = (const float*)d_in[1];
    const float* refs = (const float*)d_in[2];
    const float* intr = (const float*)d_in[3];
    const float* extr = (const float*)d_in[4];
    const float* qin  = (const float*)d_in[5];
    const float* Wq   = (const float*)d_in[6];
    const float* bq   = (const float*)d_in[7];
    const float* Wk   = (const float*)d_in[8];
    const float* bk   = (const float*)d_in[9];
    const float* Wv   = (const float*)d_in[10];
    const float* bv   = (const float*)d_in[11];
    const float* Wo   = (const float*)d_in[12];
    const float* bo   = (const float*)d_in[13];
    float* out = (float*)d_out;

    // 1. NHWC transposes
    {
        dim3 blk(32, 8);
        dim3 g0((H0 * W0) / 32, CH / 32, BATCH * VIEWS);
        transpose_nhwc_kernel<<<g0, blk>>>(f0, H0 * W0, 0);
        dim3 g1((H1 * W1) / 32, CH / 32, BATCH * VIEWS);
        transpose_nhwc_kernel<<<g1, blk>>>(f1, H1 * W1, 1);
    }

    // 2. Sampler -> g_ctx
    sampler_kernel<<<BATCH * NQ, CH>>>(refs, intr, extr);

    // 3. Fused QKV projections
    const int M = BATCH * NQ;  // 1800
    {
        dim3 ggrid(CH / 64, (M + 63) / 64, 3);
        gemm_qkv_kernel<<<ggrid, 256>>>(qin, Wq, bq, Wk, bk, Wv, bv, M);
    }

    // 4. Attention
    attn_kernel<<<dim3((NQ + ATQ - 1) / ATQ, HEADS, BATCH), 256>>>();

    // 5. Output projection -> d_out
    {
        dim3 ggrid(CH / 64, (M + 63) / 64);
        gemm_o_kernel<<<ggrid, 256>>>(Wo, bo, out, M);
    }
}